// round 4
// baseline (speedup 1.0000x reference)
#include <cuda_runtime.h>
#include <stdint.h>

// EmbeddingDropout, fused single kernel:
// out[tok,:] = W[words[tok],:] * keep(words[tok])
// keep(v) via JAX partitionable threefry2x32, key=(0,42):
//   (o0,o1) = threefry2x32(x0=0, x1=v); bits = o0^o1
//   u = bitcast((bits>>9)|0x3f800000)-1 ; keep = (u>=0.1) ? 1/0.9 : 0

#define D_EMB 1024

__device__ __forceinline__ uint32_t rotl32(uint32_t v, int d) {
    return (v << d) | (v >> (32 - d));
}

__device__ __forceinline__ float keep_of_row(uint32_t x1) {
    const uint32_t ks1 = 42u;
    const uint32_t ks2 = 42u ^ 0x1BD11BDAu;
    uint32_t x0 = 0u;
    x1 += ks1;
#define TF_ROUND(r) { x0 += x1; x1 = rotl32(x1, (r)); x1 ^= x0; }
    TF_ROUND(13) TF_ROUND(15) TF_ROUND(26) TF_ROUND(6)
    x0 += ks1; x1 += ks2 + 1u;
    TF_ROUND(17) TF_ROUND(29) TF_ROUND(16) TF_ROUND(24)
    x0 += ks2; x1 += 0u + 2u;
    TF_ROUND(13) TF_ROUND(15) TF_ROUND(26) TF_ROUND(6)
    x0 += 0u; x1 += ks1 + 3u;
    TF_ROUND(17) TF_ROUND(29) TF_ROUND(16) TF_ROUND(24)
    x0 += ks1; x1 += ks2 + 4u;
    TF_ROUND(13) TF_ROUND(15) TF_ROUND(26) TF_ROUND(6)
    x0 += ks2; x1 += 0u + 5u;
#undef TF_ROUND
    uint32_t bits = x0 ^ x1;
    float u = __uint_as_float((bits >> 9) | 0x3f800000u) - 1.0f;
    return (u >= 0.1f) ? (1.0f / 0.9f) : 0.0f;
}

// Two tokens per warp: 16 independent LDG.128 in flight per thread-slot,
// all issued before any store. Lane l covers float4 slots l, l+32, ..., l+224
// of each row.
__global__ void gather_kernel(const int* __restrict__ words,
                              const float* __restrict__ W,
                              float* __restrict__ out,
                              int n_tokens) {
    int warp_id = (blockIdx.x * blockDim.x + threadIdx.x) >> 5;
    int lane = threadIdx.x & 31;
    int tok0 = warp_id * 2;
    if (tok0 >= n_tokens) return;

    int row0 = __ldg(&words[tok0]);
    int row1 = __ldg(&words[tok0 + 1]);

    const float4* __restrict__ src0 =
        reinterpret_cast<const float4*>(W + (size_t)row0 * D_EMB);
    const float4* __restrict__ src1 =
        reinterpret_cast<const float4*>(W + (size_t)row1 * D_EMB);

    float4 v0[8], v1[8];
#pragma unroll
    for (int j = 0; j < 8; j++) v0[j] = src0[lane + 32 * j];
#pragma unroll
    for (int j = 0; j < 8; j++) v1[j] = src1[lane + 32 * j];

    float k0 = keep_of_row((uint32_t)row0);
    float k1 = keep_of_row((uint32_t)row1);

    float4* __restrict__ dst0 =
        reinterpret_cast<float4*>(out + (size_t)tok0 * D_EMB);
    float4* __restrict__ dst1 =
        reinterpret_cast<float4*>(out + (size_t)(tok0 + 1) * D_EMB);

#pragma unroll
    for (int j = 0; j < 8; j++) {
        v0[j].x *= k0; v0[j].y *= k0; v0[j].z *= k0; v0[j].w *= k0;
        __stcs(&dst0[lane + 32 * j], v0[j]);
    }
#pragma unroll
    for (int j = 0; j < 8; j++) {
        v1[j].x *= k1; v1[j].y *= k1; v1[j].z *= k1; v1[j].w *= k1;
        __stcs(&dst1[lane + 32 * j], v1[j]);
    }
}

extern "C" void kernel_launch(void* const* d_in, const int* in_sizes, int n_in,
                              void* d_out, int out_size) {
    const int*   words = (const int*)d_in[0];   // [32, 2048] int32
    const float* W     = (const float*)d_in[1]; // [50257, 1024] f32
    float*       out   = (float*)d_out;         // [32, 2048, 1024] f32

    int n_tokens = in_sizes[0];                 // 65536
    // 8 warps per 256-thread block, 2 tokens per warp -> 16 tokens/block
    int blocks = (n_tokens + 15) / 16;
    gather_kernel<<<blocks, 256>>>(words, W, out, n_tokens);
}